// round 13
// baseline (speedup 1.0000x reference)
#include <cuda_runtime.h>
#include <math.h>

typedef unsigned long long u64t;

#define FDIM  256
#define HDIM  1024
#define NX    65536
#define NB    128
#define NT    1024

// ---------------- persistent device state (no allocations) ----------------
__device__ float g_xbuf[2][NX];          // ping-pong x / x5
__device__ float g_k[8][NX];             // RK stage ring (FSAL rotation)
__device__ float g_p[NB*32*256];         // GEMM2 partials [slab][slice][32][256]
__device__ float g_part[NB];             // per-block error partials
__device__ unsigned g_bar;               // cumulative grid-barrier counter

// ---------------- Dormand-Prince tableau ----------------------------------
__constant__ float c_A[7][6] = {
  {0,0,0,0,0,0},
  {(float)(1.0/5.0),0,0,0,0,0},
  {(float)(3.0/40.0),(float)(9.0/40.0),0,0,0,0},
  {(float)(44.0/45.0),(float)(-56.0/15.0),(float)(32.0/9.0),0,0,0},
  {(float)(19372.0/6561.0),(float)(-25360.0/2187.0),(float)(64448.0/6561.0),(float)(-212.0/729.0),0,0},
  {(float)(9017.0/3168.0),(float)(-355.0/33.0),(float)(46732.0/5247.0),(float)(49.0/176.0),(float)(-5103.0/18656.0),0},
  {(float)(35.0/384.0),0.0f,(float)(500.0/1113.0),(float)(125.0/192.0),(float)(-2187.0/6784.0),(float)(11.0/84.0)},
};
__constant__ float c_C[7]  = {0.f,0.2f,0.3f,0.8f,(float)(8.0/9.0),1.f,1.f};
__constant__ float c_B5[7] = {(float)(35.0/384.0),0.f,(float)(500.0/1113.0),(float)(125.0/192.0),
                              (float)(-2187.0/6784.0),(float)(11.0/84.0),0.f};
__constant__ float c_D[7]  = {
  (float)(35.0/384.0 - 5179.0/57600.0),
  0.f,
  (float)(500.0/1113.0 - 7571.0/16695.0),
  (float)(125.0/192.0 - 393.0/640.0),
  (float)(-2187.0/6784.0 + 92097.0/339200.0),
  (float)(11.0/84.0 - 187.0/2100.0),
  (float)(-1.0/40.0)};

// ---------------- shared-memory layout (floats) ----------------------------
#define OFF_W1T  0                      // [64][258]  W1 slice, transposed (k contig)
#define OFF_W2T  16512                  // [256][66]  W2 slice, transposed
#define OFF_W1TM 33408                  // [64] time row
#define OFF_B1   33472                  // [64]
#define OFF_B2   33536                  // [256]
#define OFF_SA   33792                  // [8320] xi slab [32][260] / kz partials / reductions
#define OFF_HB   42112                  // [32][68] h_blk (padded)
#define SM_FLOATS 44288
#define SMEM_BYTES (SM_FLOATS*4)

// ---------------- packed f32x2 FMA (sm_100+ PTX) ---------------------------
__device__ __forceinline__ u64t f2fma(u64t a, u64t b, u64t c) {
  u64t d;
  asm("fma.rn.f32x2 %0, %1, %2, %3;" : "=l"(d) : "l"(a), "l"(b), "l"(c));
  return d;
}
__device__ __forceinline__ float f2fold(u64t v) {
  union { u64t u; float2 f; } cv; cv.u = v;
  return cv.f.x + cv.f.y;
}

// ---------------- init: reset state every graph replay ---------------------
__global__ void k_init(const float* __restrict__ x0, float* __restrict__ out) {
  int i = blockIdx.x*blockDim.x + threadIdx.x;
  if (i < NX) { g_xbuf[0][i] = x0[i]; out[i] = x0[i]; }
  if (i == 0) g_bar = 0u;
}

// ---------------- software grid barrier ------------------------------------
__device__ __forceinline__ void gridbar() {
  __syncthreads();
  if (threadIdx.x == 0) {
    __threadfence();
    unsigned gen = atomicAdd(&g_bar, 1u);
    unsigned target = gen - (gen % NB) + NB;
    unsigned v;
    do {
      asm volatile("ld.acquire.gpu.u32 %0, [%1];" : "=r"(v) : "l"(&g_bar) : "memory");
    } while ((int)(v - target) < 0);
    __threadfence();
  }
  __syncthreads();
}

// ---------------- persistent solver kernel ---------------------------------
__global__ void __launch_bounds__(NT, 1) k_ode(
    const float* __restrict__ W1, const float* __restrict__ b1,
    const float* __restrict__ W2, const float* __restrict__ b2,
    float* __restrict__ out)
{
  extern __shared__ float sm[];
  const int b = blockIdx.x, tid = threadIdx.x;
  const int slab = b >> 4, slice = b & 15;
  const int bHn = slice * 64;

  float* W1T = sm + OFF_W1T;
  float* W2T = sm + OFF_W2T;
  float* w1t = sm + OFF_W1TM;
  float* b1s = sm + OFF_B1;
  float* b2s = sm + OFF_B2;
  float* sA  = sm + OFF_SA;
  float* hB  = sm + OFF_HB;

  // ---- prologue: weights resident (transposed) in SMEM ---------------------
  for (int i = tid; i < 64*256; i += NT) {       // i = k*64 + c
    int k = i >> 6, c = i & 63;
    W1T[c*258 + k] = W1[k*HDIM + bHn + c];
  }
  for (int i = tid; i < 64*256; i += NT) {       // i = k*256 + c
    int k = i >> 8, c = i & 255;
    W2T[c*66 + k] = W2[(bHn + k)*FDIM + c];
  }
  if (tid < 64) { w1t[tid] = W1[FDIM*HDIM + bHn + tid]; b1s[tid] = b1[bHn + tid]; }
  if (tid < 256) b2s[tid] = b2[tid];
  __syncthreads();

  const int wid = tid >> 5, lane = tid & 31;
  const int rs = lane >> 4, cg = lane & 15;

  // block-local solver scalars (identical across blocks by construction)
  float t = 0.f, dt = 0.05f;
  int par = 0, kbase = 0, fsal = 0;

  for (int it = 0; it < 64; it++) {
    if (t >= 1.0f) break;                         // uniform across grid
    float dt_c = fmaxf(fminf(dt, 1.0f - t), 0.0f);
    const float* cur = g_xbuf[par];
    float*       nxt = g_xbuf[par ^ 1];

    for (int s = fsal ? 1 : 0; s < 7; s++) {
      // ======== xi slab build: [32][260] into sA ==========================
      {
        float ca[6];
        #pragma unroll
        for (int j = 0; j < 6; j++) ca[j] = dt_c * c_A[s][j];
        #pragma unroll
        for (int c4 = 0; c4 < 2; c4++) {
          int i4 = c4*4096 + tid*4;
          int m = i4 >> 8, kk = i4 & 255;
          int gi = (slab*32 + m)*FDIM + kk;
          float4 v = *(const float4*)&cur[gi];
          for (int j = 0; j < s; j++) {
            float4 kv = *(const float4*)&g_k[(kbase + j) & 7][gi];
            v.x = fmaf(ca[j], kv.x, v.x);
            v.y = fmaf(ca[j], kv.y, v.y);
            v.z = fmaf(ca[j], kv.z, v.z);
            v.w = fmaf(ca[j], kv.w, v.w);
          }
          *(float4*)&sA[m*260 + kk] = v;
        }
      }
      __syncthreads();

      // ======== GEMM1: h_blk = tanh(xi @ W1slice), f32x2 packed ===========
      // 32 warps = kz(4) x wp(8); warp = 8 rows x 32 cols; thread 4r x 2c, K-span 64
      {
        const int kz = wid & 3, wp = wid >> 2;
        const int r0 = (wp >> 1)*8 + rs*4;
        const int cbase = (wp & 1)*32 + cg;
        const float* A0 = &sA[(r0+0)*260 + kz*64];
        const float* A1 = &sA[(r0+1)*260 + kz*64];
        const float* A2 = &sA[(r0+2)*260 + kz*64];
        const float* A3 = &sA[(r0+3)*260 + kz*64];
        const float* B0 = &W1T[cbase*258 + kz*64];
        const float* B1p= &W1T[(cbase+16)*258 + kz*64];
        u64t acc[4][2];
        #pragma unroll
        for (int r = 0; r < 4; r++) { acc[r][0] = 0ULL; acc[r][1] = 0ULL; }

        #pragma unroll 4
        for (int k = 0; k < 64; k += 4) {
          union { float4 f; u64t u[2]; } a0,a1,a2,a3;
          a0.f = *(const float4*)(A0+k);
          a1.f = *(const float4*)(A1+k);
          a2.f = *(const float4*)(A2+k);
          a3.f = *(const float4*)(A3+k);
          #pragma unroll
          for (int p = 0; p < 2; p++) {
            u64t w0 = *(const u64t*)(B0 +k+2*p);
            u64t w1 = *(const u64t*)(B1p+k+2*p);
            acc[0][0]=f2fma(a0.u[p],w0,acc[0][0]); acc[0][1]=f2fma(a0.u[p],w1,acc[0][1]);
            acc[1][0]=f2fma(a1.u[p],w0,acc[1][0]); acc[1][1]=f2fma(a1.u[p],w1,acc[1][1]);
            acc[2][0]=f2fma(a2.u[p],w0,acc[2][0]); acc[2][1]=f2fma(a2.u[p],w1,acc[2][1]);
            acc[3][0]=f2fma(a3.u[p],w0,acc[3][0]); acc[3][1]=f2fma(a3.u[p],w1,acc[3][1]);
          }
        }
        __syncthreads();                 // xi dead; reuse sA for kz partials
        #pragma unroll
        for (int r = 0; r < 4; r++) {
          sA[kz*2048 + (r0+r)*64 + cbase     ] = f2fold(acc[r][0]);
          sA[kz*2048 + (r0+r)*64 + cbase + 16] = f2fold(acc[r][1]);
        }
        __syncthreads();
        // combine kz partials (fixed order) + tanh -> hB, 2 outputs/thread
        {
          float ts = t + c_C[s]*dt_c;
          int o = tid*2;
          int row = o >> 6, col = o & 63;
          float2 s0 = *(const float2*)&sA[0*2048 + o];
          float2 s1 = *(const float2*)&sA[1*2048 + o];
          float2 s2 = *(const float2*)&sA[2*2048 + o];
          float2 s3 = *(const float2*)&sA[3*2048 + o];
          float v0 = ((s0.x + s1.x) + s2.x) + s3.x;
          float v1 = ((s0.y + s1.y) + s2.y) + s3.y;
          float* hp = &hB[row*68 + col];
          hp[0] = tanhf(fmaf(ts, w1t[col+0], v0 + b1s[col+0]));
          hp[1] = tanhf(fmaf(ts, w1t[col+1], v1 + b1s[col+1]));
        }
      }
      __syncthreads();

      // ======== GEMM2 partial: p = h_blk @ W2slice, f32x2 packed ==========
      // 32 warps = wr(8) x wc(4); warp = 4 rows x 64 cols; thread 2r x 4c, full K=64
      {
        const int wr = wid >> 2, wc = wid & 3;
        const int r0 = wr*4 + rs*2;
        const float* A0 = &hB[(r0+0)*68];
        const float* A1 = &hB[(r0+1)*68];
        const float* B0 = &W2T[(wc*64 + cg +  0)*66];
        const float* B1p= &W2T[(wc*64 + cg + 16)*66];
        const float* B2p= &W2T[(wc*64 + cg + 32)*66];
        const float* B3p= &W2T[(wc*64 + cg + 48)*66];
        u64t acc[2][4];
        #pragma unroll
        for (int r = 0; r < 2; r++)
          #pragma unroll
          for (int i = 0; i < 4; i++) acc[r][i] = 0ULL;

        #pragma unroll 4
        for (int k = 0; k < 64; k += 4) {
          union { float4 f; u64t u[2]; } a0,a1;
          a0.f = *(const float4*)(A0+k);
          a1.f = *(const float4*)(A1+k);
          #pragma unroll
          for (int p = 0; p < 2; p++) {
            u64t w0 = *(const u64t*)(B0 +k+2*p);
            u64t w1 = *(const u64t*)(B1p+k+2*p);
            u64t w2 = *(const u64t*)(B2p+k+2*p);
            u64t w3 = *(const u64t*)(B3p+k+2*p);
            acc[0][0]=f2fma(a0.u[p],w0,acc[0][0]); acc[0][1]=f2fma(a0.u[p],w1,acc[0][1]);
            acc[0][2]=f2fma(a0.u[p],w2,acc[0][2]); acc[0][3]=f2fma(a0.u[p],w3,acc[0][3]);
            acc[1][0]=f2fma(a1.u[p],w0,acc[1][0]); acc[1][1]=f2fma(a1.u[p],w1,acc[1][1]);
            acc[1][2]=f2fma(a1.u[p],w2,acc[1][2]); acc[1][3]=f2fma(a1.u[p],w3,acc[1][3]);
          }
        }
        float* pb = &g_p[(b*32 + r0)*256 + wc*64 + cg];
        #pragma unroll
        for (int r = 0; r < 2; r++)
          #pragma unroll
          for (int i = 0; i < 4; i++)
            pb[r*256 + 16*i] = f2fold(acc[r][i]);
      }
      gridbar();

      // ======== reduce partials -> k_s (block's 512 elements, tid<512) ====
      {
        if (s < 6) {
          if (tid < 512) {
            const int idL = slice*512 + tid;
            const float* pp = &g_p[slab*16*8192 + idL];
            float sum = 0.f;
            #pragma unroll
            for (int sl = 0; sl < 16; sl++) sum += pp[sl*8192];
            sum += b2s[idL & 255];
            g_k[(kbase + s) & 7][slab*8192 + idL] = sum;
          }
          gridbar();
        } else {
          // stage-6 fused with x5/err (k6 consumed in-register)
          float rsq = 0.f;
          if (tid < 512) {
            const int idL = slice*512 + tid;
            const float* pp = &g_p[slab*16*8192 + idL];
            float sum = 0.f;
            #pragma unroll
            for (int sl = 0; sl < 16; sl++) sum += pp[sl*8192];
            sum += b2s[idL & 255];
            const int gi = slab*8192 + idL;
            g_k[(kbase + 6) & 7][gi] = sum;      // FSAL slot for next iteration
            float cb[7], cd[7];
            #pragma unroll
            for (int j = 0; j < 7; j++) { cb[j] = dt_c*c_B5[j]; cd[j] = dt_c*c_D[j]; }
            float x = cur[gi], x5 = x, err = 0.f;
            #pragma unroll
            for (int j = 0; j < 6; j++) {
              float kv = g_k[(kbase + j) & 7][gi];
              x5  = fmaf(cb[j], kv, x5);
              err = fmaf(cd[j], kv, err);
            }
            x5  = fmaf(cb[6], sum, x5);
            err = fmaf(cd[6], sum, err);
            nxt[gi] = x5;
            float scale = fmaf(1e-3f, fmaxf(fabsf(x), fabsf(x5)), 1e-4f);
            float r = err / scale;
            rsq = r*r;
          }
          sA[tid] = rsq;
          __syncthreads();
          #pragma unroll
          for (int st = 512; st > 0; st >>= 1) {
            if (tid < st) sA[tid] += sA[tid + st];
            __syncthreads();
          }
          if (tid == 0) g_part[b] = sA[0];
        }
      }
    }
    gridbar();

    // ======== finalize (replicated in every block, identical fp) ==========
    {
      sA[tid] = (tid < NB) ? g_part[tid] : 0.f;
      __syncthreads();
      #pragma unroll
      for (int st = 64; st > 0; st >>= 1) {
        if (tid < st) sA[tid] += sA[tid + st];
        __syncthreads();
      }
      float err_norm = sqrtf(sA[0] * (1.0f/(float)NX));
      __syncthreads();                          // protect sA[0] before reuse
      int accept = (err_norm <= 1.0f);
      float factor = 0.9f * powf(err_norm + 1e-10f, -0.2f);
      factor = fminf(fmaxf(factor, 0.2f), 5.0f);
      if (accept) { t = t + dt_c; par ^= 1; kbase = (kbase + 6) & 7; }
      dt = dt_c * factor;
      fsal = 1;   // k0 stays valid on reject too (x, t unchanged)
    }
  }

  // ---- write final trajectory row ----------------------------------------
  if (tid < 512) {
    int gi = slab*8192 + slice*512 + tid;
    out[NX + gi] = g_xbuf[par][gi];
  }
}

extern "C" void kernel_launch(void* const* d_in, const int* in_sizes, int n_in,
                              void* d_out, int out_size) {
  const float* x0 = (const float*)d_in[0];
  const float* W1 = (const float*)d_in[1];
  const float* b1 = (const float*)d_in[2];
  const float* W2 = (const float*)d_in[3];
  const float* b2 = (const float*)d_in[4];
  float* out = (float*)d_out;

  cudaFuncSetAttribute(k_ode, cudaFuncAttributeMaxDynamicSharedMemorySize, SMEM_BYTES);
  k_init<<<64, 1024>>>(x0, out);
  k_ode<<<NB, NT, SMEM_BYTES>>>(W1, b1, W2, b2, out);
}